// round 6
// baseline (speedup 1.0000x reference)
#include <cuda_runtime.h>

typedef unsigned long long u64;
#define NPOS 65536
#define NPOSf 65536.0f
#define NPART 16
#define PBLOCKS 512
#define PTHREADS 128

// persistent scratch (device globals)
__device__ float2 g_x2[16 * NPOS];              // residual stream, ch-paired
__device__ float2 g_r2[16 * NPOS];              // pre-BN layer-0 output, ch-paired
__device__ float  g_z[128 * NPOS];              // end_conv1 output
__device__ float  g_statp[NPART][42][2][128];   // partitioned stats
__device__ unsigned g_barcnt;
__device__ volatile unsigned g_bargen;

__device__ __forceinline__ float* stat_ptr(int part, int op, int kind) {
    return &g_statp[part][op][kind][0];
}

__device__ __forceinline__ void fma2(u64 &d, u64 a, u64 b, u64 c) {
    asm("fma.rn.f32x2 %0, %1, %2, %3;" : "=l"(d) : "l"(a), "l"(b), "l"(c));
}
__device__ __forceinline__ u64 pack2(float f) {
    u64 r; unsigned b = __float_as_uint(f);
    asm("mov.b64 %0, {%1, %1};" : "=l"(r) : "r"(b));
    return r;
}
__device__ __forceinline__ float lo2(u64 v) { return __uint_as_float((unsigned)v); }
__device__ __forceinline__ float hi2(u64 v) { return __uint_as_float((unsigned)(v >> 32)); }

__device__ __forceinline__ float mishf(float v) {
    float u = __expf(fminf(fmaxf(v, -20.0f), 20.0f));
    float w = fmaf(u, u, u + u);
    return v * __fdividef(w, w + 2.0f);
}

// mish(a) and mish(-a) sharing one exp
__device__ __forceinline__ void mish_pair(float a, float &mp, float &mn) {
    float ac = fminf(fmaxf(a, -20.0f), 20.0f);
    float u = __expf(ac);
    float A = fmaf(u, u, u + u);
    mp = a * __fdividef(A, A + 2.0f);
    float B = fmaf(2.0f, u, 1.0f);
    mn = -a * __fdividef(B, fmaf(u + u, u, B));
}

// fused single-pass sum/sumsq block reduction of vals[32] over BS threads.
template<int BS>
__device__ __forceinline__ void reduce_stats(float* red, float* part1, float* part2,
                                             const float* vals, int tid,
                                             int prt, int op, int coff) {
    __syncthreads();
    #pragma unroll
    for (int c = 0; c < 32; c++) red[tid * 34 + c] = vals[c];
    __syncthreads();
    {
        int c = tid & 31, seg = tid >> 5;
        int base = seg * 32;
        float s = 0.f, q = 0.f;
        #pragma unroll
        for (int r = 0; r < 32; r++) {
            float v = red[(base + r) * 34 + c];
            s += v;
            q = fmaf(v, v, q);
        }
        part1[seg * 32 + c] = s;
        part2[seg * 32 + c] = q;
    }
    __syncthreads();
    if (tid < 64) {
        int c = tid & 31, kind = tid >> 5;
        const float* pp = kind ? part2 : part1;
        float t = 0.f;
        #pragma unroll
        for (int sg = 0; sg < BS / 32; sg++) t += pp[sg * 32 + c];
        atomicAdd(stat_ptr(prt, op, kind) + coff + c, t);
    }
}

// combine partitioned stats -> BN scale/shift (threads 0..31), plain loads
__device__ __forceinline__ void bn_combine32(const float* g, const float* b, int op,
                                             float* s_scale, float* s_shift, int tid) {
    if (tid < 32) {
        float s = 0.f, q = 0.f;
        #pragma unroll
        for (int pp = 0; pp < NPART; pp++) {
            s += g_statp[pp][op][0][tid];
            q += g_statp[pp][op][1][tid];
        }
        float m = s * (1.0f / NPOSf);
        float var = q * (1.0f / NPOSf) - m * m;
        float inv = rsqrtf(var + 1e-5f);
        float sc = g[tid] * inv;
        s_scale[tid] = sc;
        s_shift[tid] = b[tid] - m * sc;
    }
}

// L2-coherent variant for use inside the persistent kernel (post grid barrier)
__device__ __forceinline__ void bn_combine32_cg(const float* g, const float* b, int op,
                                                float* s_scale, float* s_shift, int tid) {
    if (tid < 32) {
        float s = 0.f, q = 0.f;
        #pragma unroll
        for (int pp = 0; pp < NPART; pp++) {
            s += __ldcg(&g_statp[pp][op][0][tid]);
            q += __ldcg(&g_statp[pp][op][1][tid]);
        }
        float m = s * (1.0f / NPOSf);
        float var = q * (1.0f / NPOSf) - m * m;
        float inv = rsqrtf(var + 1e-5f);
        float sc = g[tid] * inv;
        s_scale[tid] = sc;
        s_shift[tid] = b[tid] - m * sc;
    }
}

// full-width paired gate(16x32)->concat-mish->res(32x32) per position-thread
__device__ __forceinline__ void gate_res_p(const float* xn, float* rn,
                                           const float* s_gw, const float* s_gb,
                                           const float* s_rw, const float* s_rb) {
    u64 accg[8];
    #pragma unroll
    for (int jp = 0; jp < 8; jp++) accg[jp] = *(const u64*)&s_gb[2 * jp];
    const ulonglong2* gw2 = (const ulonglong2*)s_gw;
    #pragma unroll
    for (int k = 0; k < 32; k++) {
        u64 xk = pack2(xn[k]);
        #pragma unroll
        for (int m = 0; m < 4; m++) {
            ulonglong2 w = gw2[k * 4 + m];
            fma2(accg[2 * m],     w.x, xk, accg[2 * m]);
            fma2(accg[2 * m + 1], w.y, xk, accg[2 * m + 1]);
        }
    }
    float cm[32];
    #pragma unroll
    for (int jp = 0; jp < 8; jp++) {
        float a0 = lo2(accg[jp]), a1 = hi2(accg[jp]);
        mish_pair(a0, cm[2 * jp],     cm[2 * jp + 16]);
        mish_pair(a1, cm[2 * jp + 1], cm[2 * jp + 17]);
    }
    u64 accr[16];
    #pragma unroll
    for (int cp = 0; cp < 16; cp++) accr[cp] = *(const u64*)&s_rb[2 * cp];
    const ulonglong2* rw2 = (const ulonglong2*)s_rw;
    #pragma unroll
    for (int k = 0; k < 32; k++) {
        u64 ck = pack2(cm[k]);
        #pragma unroll
        for (int m = 0; m < 8; m++) {
            ulonglong2 w = rw2[k * 8 + m];
            fma2(accr[2 * m],     w.x, ck, accr[2 * m]);
            fma2(accr[2 * m + 1], w.y, ck, accr[2 * m + 1]);
        }
    }
    #pragma unroll
    for (int cp = 0; cp < 16; cp++) {
        rn[2 * cp]     = lo2(accr[cp]);
        rn[2 * cp + 1] = hi2(accr[cp]);
    }
}

__global__ void k_prep() {
    int idx = blockIdx.x * 512 + threadIdx.x;
    float* st = &g_statp[0][0][0][0];
    if (idx < NPART * 42 * 2 * 128) st[idx] = 0.f;
    if (idx == 0) { g_barcnt = 0; g_bargen = 0; }
}

// start conv (32x256) + layer-0 gate/res + stats[0]
__global__ __launch_bounds__(256, 2) void k_start(
    const float* __restrict__ xin,
    const float* __restrict__ start_w, const float* __restrict__ start_b,
    const float* __restrict__ gate_w, const float* __restrict__ gate_b,
    const float* __restrict__ res_w, const float* __restrict__ res_b)
{
    __shared__ __align__(16) float s_red[256 * 34];   // swT alias / reduction
    __shared__ float s_p1[256], s_p2[256];
    __shared__ __align__(16) float s_gw[512];
    __shared__ __align__(16) float s_rw[1024];
    __shared__ __align__(8) float s_gb[16];
    __shared__ __align__(8) float s_rb[32];
    __shared__ __align__(8) float s_sb[32];

    int tid = threadIdx.x;
    int p = blockIdx.x * 256 + tid;
    int prt = blockIdx.x & (NPART - 1);

    for (int idx = tid; idx < 8192; idx += 256) {
        int k = idx >> 5, c = idx & 31;
        s_red[k * 32 + c] = start_w[c * 256 + k];
    }
    for (int i = tid; i < 512; i += 256)  { int j = i & 15, k = i >> 4; s_gw[i] = gate_w[j * 32 + k]; }
    for (int i = tid; i < 1024; i += 256) { int c = i & 31, k = i >> 5; s_rw[i] = res_w[c * 32 + k]; }
    if (tid < 16) s_gb[tid] = gate_b[tid];
    if (tid >= 32 && tid < 64) s_rb[tid - 32] = res_b[tid - 32];
    if (tid >= 64 && tid < 96) s_sb[tid - 64] = start_b[tid - 64];
    __syncthreads();

    u64 acc[16];
    #pragma unroll
    for (int cp = 0; cp < 16; cp++) acc[cp] = *(const u64*)&s_sb[2 * cp];
    const float* xp = xin + (size_t)(p & 7) * (256 * 8192) + (p >> 3);
    const ulonglong2* swT2 = (const ulonglong2*)s_red;
    #pragma unroll 4
    for (int k = 0; k < 256; k++) {
        u64 xk = pack2(xp[k * 8192]);
        #pragma unroll
        for (int m = 0; m < 8; m++) {
            ulonglong2 w = swT2[k * 8 + m];
            fma2(acc[2 * m],     w.x, xk, acc[2 * m]);
            fma2(acc[2 * m + 1], w.y, xk, acc[2 * m + 1]);
        }
    }
    float xn[32];
    #pragma unroll
    for (int cp = 0; cp < 16; cp++) {
        xn[2 * cp] = lo2(acc[cp]);
        xn[2 * cp + 1] = hi2(acc[cp]);
        g_x2[cp * NPOS + p] = make_float2(xn[2 * cp], xn[2 * cp + 1]);
    }
    float rn[32];
    gate_res_p(xn, rn, s_gw, s_gb, s_rw, s_rb);
    #pragma unroll
    for (int cp = 0; cp < 16; cp++) g_r2[cp * NPOS + p] = make_float2(rn[2 * cp], rn[2 * cp + 1]);

    reduce_stats<256>(s_red, s_p1, s_p2, rn, tid, prt, 0, 0);
}

// ============ persistent mid-network kernel: layers 1..39 + endA ============
// weight buffer layout: [0,512) gwT | [512,1536) rwT | [1536,1552) gb | [1552,1584) rb
__device__ __forceinline__ void load_wbuf(float* buf,
                                          const float* gw, const float* gb,
                                          const float* rw, const float* rb,
                                          int layer, int tid) {
    #pragma unroll
    for (int i = tid; i < 512; i += PTHREADS) {
        int j = i & 15, k = i >> 4;
        buf[i] = gw[layer * 512 + j * 32 + k];
    }
    #pragma unroll
    for (int i = tid; i < 1024; i += PTHREADS) {
        int c = i & 31, k = i >> 5;
        buf[512 + i] = rw[layer * 1024 + c * 32 + k];
    }
    if (tid < 16) buf[1536 + tid] = gb[layer * 16 + tid];
    if (tid >= 64 && tid < 96) buf[1552 + tid - 64] = rb[layer * 32 + tid - 64];
}

__device__ __forceinline__ void gridbar(unsigned &gen) {
    __syncthreads();
    if (threadIdx.x == 0) {
        __threadfence();
        unsigned a = atomicAdd(&g_barcnt, 1u);
        if (a == PBLOCKS - 1) {
            atomicExch(&g_barcnt, 0u);
            __threadfence();
            g_bargen = gen + 1;
        } else {
            while (g_bargen == gen) { __nanosleep(128); }
        }
        __threadfence();
    }
    __syncthreads();
    gen++;
}

__global__ __launch_bounds__(PTHREADS, 4) void k_mid(
    const float* __restrict__ gate_w, const float* __restrict__ gate_b,
    const float* __restrict__ res_w, const float* __restrict__ res_b,
    const float* __restrict__ bn_g, const float* __restrict__ bn_b)
{
    __shared__ __align__(16) float s_w[2][1584];
    __shared__ __align__(16) float s_red[PTHREADS * 34];
    __shared__ float s_p1[PTHREADS], s_p2[PTHREADS];
    __shared__ float s_scale[32], s_shift[32];

    int tid = threadIdx.x;
    int p = blockIdx.x * PTHREADS + tid;
    int prt = blockIdx.x & (NPART - 1);

    // residual state in registers for the whole loop
    float x[32], r[32];
    #pragma unroll
    for (int cp = 0; cp < 16; cp++) {
        float2 xv = g_x2[cp * NPOS + p];
        float2 rv = g_r2[cp * NPOS + p];
        x[2 * cp] = xv.x; x[2 * cp + 1] = xv.y;
        r[2 * cp] = rv.x; r[2 * cp + 1] = rv.y;
    }
    load_wbuf(s_w[1], gate_w, gate_b, res_w, res_b, 1, tid);

    unsigned gen = 0;
    for (int layer = 1; layer < 40; layer++) {
        // stats[layer-1] complete: layer 1 via kernel boundary, else via gridbar
        bn_combine32_cg(bn_g + (layer - 1) * 32, bn_b + (layer - 1) * 32,
                        layer - 1, s_scale, s_shift, tid);
        __syncthreads();
        #pragma unroll
        for (int c = 0; c < 32; c++)
            x[c] = fmaf(s_scale[c], r[c], x[c] + s_shift[c]);

        const float* buf = s_w[layer & 1];
        gate_res_p(x, r, buf, buf + 1536, buf + 512, buf + 1552);

        reduce_stats<PTHREADS>(s_red, s_p1, s_p2, r, tid, prt, layer, 0);

        if (layer < 39)
            load_wbuf(s_w[(layer + 1) & 1], gate_w, gate_b, res_w, res_b,
                      layer + 1, tid);
        gridbar(gen);
    }

    // endA: BN(stats[39]) + residual -> final x; write g_x2; stats[40]
    bn_combine32_cg(bn_g + 39 * 32, bn_b + 39 * 32, 39, s_scale, s_shift, tid);
    __syncthreads();
    #pragma unroll
    for (int c = 0; c < 32; c++)
        x[c] = fmaf(s_scale[c], r[c], x[c] + s_shift[c]);
    #pragma unroll
    for (int cp = 0; cp < 16; cp++)
        g_x2[cp * NPOS + p] = make_float2(x[2 * cp], x[2 * cp + 1]);

    reduce_stats<PTHREADS>(s_red, s_p1, s_p2, x, tid, prt, 40, 0);
}

// y = concat_mish(bn1(x)); z = end_conv1(128x64) @ y; stats[41]
__global__ __launch_bounds__(256, 2) void k_endB(
    const float* __restrict__ bn1_g, const float* __restrict__ bn1_b,
    const float* __restrict__ w1, const float* __restrict__ b1)
{
    __shared__ __align__(16) float s_red[256 * 34];
    __shared__ float s_p1[256], s_p2[256];
    __shared__ __align__(16) float s_w[2048];
    __shared__ float s_scale[32], s_shift[32];
    __shared__ __align__(8) float s_b1[128];
    int tid = threadIdx.x;
    int p = blockIdx.x * 256 + tid;
    int prt = blockIdx.x & (NPART - 1);
    bn_combine32(bn1_g, bn1_b, 40, s_scale, s_shift, tid);
    if (tid < 128) s_b1[tid] = b1[tid];
    __syncthreads();

    float y[64];
    #pragma unroll
    for (int cp = 0; cp < 16; cp++) {
        float2 xv = g_x2[cp * NPOS + p];
        float t0 = fmaf(s_scale[2 * cp],     xv.x, s_shift[2 * cp]);
        float t1 = fmaf(s_scale[2 * cp + 1], xv.y, s_shift[2 * cp + 1]);
        mish_pair(t0, y[2 * cp],     y[2 * cp + 32]);
        mish_pair(t1, y[2 * cp + 1], y[2 * cp + 33]);
    }
    for (int chunk = 0; chunk < 4; chunk++) {
        __syncthreads();
        for (int i = tid; i < 2048; i += 256) {
            int cc = i & 31, k = i >> 5;
            s_w[i] = w1[(chunk * 32 + cc) * 64 + k];
        }
        __syncthreads();
        u64 accz[16];
        #pragma unroll
        for (int cp = 0; cp < 16; cp++) accz[cp] = *(const u64*)&s_b1[chunk * 32 + 2 * cp];
        const ulonglong2* wv2 = (const ulonglong2*)s_w;
        #pragma unroll
        for (int k = 0; k < 64; k++) {
            u64 yk = pack2(y[k]);
            #pragma unroll
            for (int m = 0; m < 8; m++) {
                ulonglong2 w = wv2[k * 8 + m];
                fma2(accz[2 * m],     w.x, yk, accz[2 * m]);
                fma2(accz[2 * m + 1], w.y, yk, accz[2 * m + 1]);
            }
        }
        float zz[32];
        #pragma unroll
        for (int cp = 0; cp < 16; cp++) {
            zz[2 * cp] = lo2(accz[cp]);
            zz[2 * cp + 1] = hi2(accz[cp]);
            g_z[(chunk * 32 + 2 * cp) * NPOS + p] = zz[2 * cp];
            g_z[(chunk * 32 + 2 * cp + 1) * NPOS + p] = zz[2 * cp + 1];
        }
        reduce_stats<256>(s_red, s_p1, s_p2, zz, tid, prt, 41, chunk * 32);
    }
}

// out = end_conv2 (256x256) @ concat_mish(bn2(z)); f32x2 packed FMA.
__global__ __launch_bounds__(256) void k_endC(
    const float* __restrict__ bn2_g, const float* __restrict__ bn2_b,
    const float* __restrict__ w2, const float* __restrict__ b2,
    float* __restrict__ out)
{
    __shared__ __align__(16) float sBuf[256 * 33 + 32 * 64];
    __shared__ float sSc[128], sSh[128], sB2[256];
    float* sW = sBuf;
    float* sV = sBuf + 256 * 33;

    int tid = threadIdx.x;
    int ty = tid >> 3;
    int tx = tid & 7;
    int p0 = blockIdx.x * 64;
    int l0 = p0 >> 3;

    if (tid < 128) {
        float s = 0.f, q = 0.f;
        #pragma unroll
        for (int pp = 0; pp < NPART; pp++) {
            s += g_statp[pp][41][0][tid];
            q += g_statp[pp][41][1][tid];
        }
        float m = s * (1.0f / NPOSf);
        float var = q * (1.0f / NPOSf) - m * m;
        float inv = rsqrtf(var + 1e-5f);
        float sc = bn2_g[tid] * inv;
        sSc[tid] = sc;
        sSh[tid] = bn2_b[tid] - m * sc;
    }
    sB2[tid] = b2[tid];

    u64 acc[8][4];
    #pragma unroll
    for (int i = 0; i < 8; i++)
        #pragma unroll
        for (int jp = 0; jp < 4; jp++) acc[i][jp] = 0ULL;

    for (int kc = 0; kc < 8; kc++) {
        __syncthreads();
        for (int idx = tid; idx < 8192; idx += 256) {
            int o = idx >> 5, k = idx & 31;
            sW[o * 33 + k] = w2[o * 256 + kc * 32 + k];
        }
        for (int idx = tid; idx < 2048; idx += 256) {
            int kk = idx >> 6, qq = idx & 63;
            int c = kc * 32 + kk;
            int zc = (c < 128) ? c : c - 128;
            float t = fmaf(sSc[zc], g_z[zc * NPOS + p0 + qq], sSh[zc]);
            sV[kk * 64 + qq] = mishf((c < 128) ? t : -t);
        }
        __syncthreads();
        int woff = ty * 8 * 33;
        int voff = tx * 8;
        #pragma unroll
        for (int k = 0; k < 32; k++) {
            u64 vv[4];
            #pragma unroll
            for (int jp = 0; jp < 4; jp++)
                vv[jp] = *(const u64*)&sV[k * 64 + voff + jp * 2];
            #pragma unroll
            for (int i = 0; i < 8; i++) {
                u64 wd = pack2(sW[woff + i * 33 + k]);
                #pragma unroll
                for (int jp = 0; jp < 4; jp++)
                    fma2(acc[i][jp], wd, vv[jp], acc[i][jp]);
            }
        }
    }

    for (int oh = 0; oh < 2; oh++) {
        __syncthreads();
        if ((ty >> 4) == oh) {
            int orow = (ty & 15) * 8;
            #pragma unroll
            for (int i = 0; i < 8; i++) {
                float bias = sB2[oh * 128 + orow + i];
                #pragma unroll
                for (int j = 0; j < 8; j++) {
                    int jp = j >> 1;
                    float f = (j & 1) ? hi2(acc[i][jp]) : lo2(acc[i][jp]);
                    sBuf[(orow + i) * 64 + j * 8 + tx] = f + bias;
                }
            }
        }
        __syncthreads();
        for (int idx = tid; idx < 2048; idx += 256) {
            int oloc = idx >> 4;
            int b = (idx >> 1) & 7;
            int hh = idx & 1;
            float4 v = *(float4*)&sBuf[oloc * 64 + b * 8 + hh * 4];
            *(float4*)&out[(size_t)b * 2097152 + (size_t)(oh * 128 + oloc) * 8192
                           + l0 + hh * 4] = v;
        }
    }
}

extern "C" void kernel_launch(void* const* d_in, const int* in_sizes, int n_in,
                              void* d_out, int out_size) {
    const float* x           = (const float*)d_in[0];
    const float* start_w     = (const float*)d_in[1];
    const float* start_b     = (const float*)d_in[2];
    const float* gate_w      = (const float*)d_in[3];
    const float* gate_b      = (const float*)d_in[4];
    const float* res_w       = (const float*)d_in[5];
    const float* res_b       = (const float*)d_in[6];
    const float* bn_g        = (const float*)d_in[7];
    const float* bn_b        = (const float*)d_in[8];
    const float* end_bn1_g   = (const float*)d_in[9];
    const float* end_bn1_b   = (const float*)d_in[10];
    const float* end_conv1_w = (const float*)d_in[11];
    const float* end_conv1_b = (const float*)d_in[12];
    const float* end_bn2_g   = (const float*)d_in[13];
    const float* end_bn2_b   = (const float*)d_in[14];
    const float* end_conv2_w = (const float*)d_in[15];
    const float* end_conv2_b = (const float*)d_in[16];
    float* out = (float*)d_out;

    k_prep<<<336, 512>>>();
    k_start<<<256, 256>>>(x, start_w, start_b, gate_w, gate_b, res_w, res_b);
    k_mid<<<PBLOCKS, PTHREADS>>>(gate_w, gate_b, res_w, res_b, bn_g, bn_b);
    k_endB<<<256, 256>>>(end_bn1_g, end_bn1_b, end_conv1_w, end_conv1_b);
    k_endC<<<1024, 256>>>(end_bn2_g, end_bn2_b, end_conv2_w, end_conv2_b, out);
}

// round 8
// speedup vs baseline: 1.4579x; 1.4579x over previous
#include <cuda_runtime.h>

typedef unsigned long long u64;
#define NPOS 65536
#define NPOSf 65536.0f
#define NPART 16

// persistent scratch (device globals)
__device__ float4 g_xr[16 * NPOS];              // (x0,x1,r0,r1) per channel-pair
__device__ float4 g_xf[8 * NPOS];               // final x, channel quads
__device__ float  g_z[128 * NPOS];              // end_conv1 output
__device__ float  g_statp[NPART][42][2][128];   // partitioned stats

__device__ __forceinline__ float* stat_ptr(int part, int op, int kind) {
    return &g_statp[part][op][kind][0];
}

__device__ __forceinline__ void fma2(u64 &d, u64 a, u64 b, u64 c) {
    asm("fma.rn.f32x2 %0, %1, %2, %3;" : "=l"(d) : "l"(a), "l"(b), "l"(c));
}
__device__ __forceinline__ u64 pack2(float f) {
    u64 r; unsigned b = __float_as_uint(f);
    asm("mov.b64 %0, {%1, %1};" : "=l"(r) : "r"(b));
    return r;
}
__device__ __forceinline__ float lo2(u64 v) { return __uint_as_float((unsigned)v); }
__device__ __forceinline__ float hi2(u64 v) { return __uint_as_float((unsigned)(v >> 32)); }

__device__ __forceinline__ float mishf(float v) {
    float u = __expf(fminf(fmaxf(v, -20.0f), 20.0f));
    float w = fmaf(u, u, u + u);
    return v * __fdividef(w, w + 2.0f);
}

// mish(a) and mish(-a) sharing one exp
__device__ __forceinline__ void mish_pair(float a, float &mp, float &mn) {
    float ac = fminf(fmaxf(a, -20.0f), 20.0f);
    float u = __expf(ac);
    float A = fmaf(u, u, u + u);
    mp = a * __fdividef(A, A + 2.0f);
    float B = fmaf(2.0f, u, 1.0f);
    mn = -a * __fdividef(B, fmaf(u + u, u, B));
}

// legacy reduction (k_start, 256 threads)
template<int BS>
__device__ __forceinline__ void reduce_stats(float* red, float* part1, float* part2,
                                             const float* vals, int tid,
                                             int prt, int op, int coff) {
    __syncthreads();
    #pragma unroll
    for (int c = 0; c < 32; c++) red[tid * 34 + c] = vals[c];
    __syncthreads();
    {
        int c = tid & 31, seg = tid >> 5;
        int base = seg * 32;
        float s = 0.f, q = 0.f;
        #pragma unroll
        for (int r = 0; r < 32; r++) {
            float v = red[(base + r) * 34 + c];
            s += v;
            q = fmaf(v, v, q);
        }
        part1[seg * 32 + c] = s;
        part2[seg * 32 + c] = q;
    }
    __syncthreads();
    if (tid < 64) {
        int c = tid & 31, kind = tid >> 5;
        const float* pp = kind ? part2 : part1;
        float t = 0.f;
        #pragma unroll
        for (int sg = 0; sg < BS / 32; sg++) t += pp[sg * 32 + c];
        atomicAdd(stat_ptr(prt, op, kind) + coff + c, t);
    }
}

// float4-vectorized reduction for 64-thread blocks; vals[32] per thread.
// red4: [8][65] float4 (transposed), ps/pq: [64] float4.
__device__ __forceinline__ void reduce64(float4* red4, float4* ps, float4* pq,
                                         const float* vals, int tid,
                                         int prt, int op) {
    __syncthreads();
    #pragma unroll
    for (int q = 0; q < 8; q++)
        red4[q * 65 + tid] = make_float4(vals[4 * q], vals[4 * q + 1],
                                         vals[4 * q + 2], vals[4 * q + 3]);
    __syncthreads();
    {
        int q = tid & 7, seg = tid >> 3;
        float4 s = make_float4(0.f, 0.f, 0.f, 0.f);
        float4 sq = make_float4(0.f, 0.f, 0.f, 0.f);
        #pragma unroll
        for (int r = 0; r < 8; r++) {
            float4 v = red4[q * 65 + seg * 8 + r];
            s.x += v.x; s.y += v.y; s.z += v.z; s.w += v.w;
            sq.x = fmaf(v.x, v.x, sq.x);
            sq.y = fmaf(v.y, v.y, sq.y);
            sq.z = fmaf(v.z, v.z, sq.z);
            sq.w = fmaf(v.w, v.w, sq.w);
        }
        ps[seg * 8 + q] = s;
        pq[seg * 8 + q] = sq;
    }
    __syncthreads();
    {
        int c = tid & 31, kind = tid >> 5;
        int quad = c >> 2, comp = c & 3;
        const float* base = (const float*)(kind ? pq : ps);
        float t = 0.f;
        #pragma unroll
        for (int seg = 0; seg < 8; seg++)
            t += base[(seg * 8 + quad) * 4 + comp];
        atomicAdd(stat_ptr(prt, op, kind) + c, t);
    }
}

// combine partitioned stats -> BN scale/shift (threads 0..31)
__device__ __forceinline__ void bn_combine32(const float* g, const float* b, int op,
                                             float* s_scale, float* s_shift, int tid) {
    if (tid < 32) {
        float s = 0.f, q = 0.f;
        #pragma unroll
        for (int pp = 0; pp < NPART; pp++) {
            s += g_statp[pp][op][0][tid];
            q += g_statp[pp][op][1][tid];
        }
        float m = s * (1.0f / NPOSf);
        float var = q * (1.0f / NPOSf) - m * m;
        float inv = rsqrtf(var + 1e-5f);
        float sc = g[tid] * inv;
        s_scale[tid] = sc;
        s_shift[tid] = b[tid] - m * sc;
    }
}

// full-width paired gate(16x32)->concat-mish->res(32x32) (k_start only)
__device__ __forceinline__ void gate_res_p(const float* xn, float* rn,
                                           const float* s_gw, const float* s_gb,
                                           const float* s_rw, const float* s_rb) {
    u64 accg[8];
    #pragma unroll
    for (int jp = 0; jp < 8; jp++) accg[jp] = *(const u64*)&s_gb[2 * jp];
    const ulonglong2* gw2 = (const ulonglong2*)s_gw;
    #pragma unroll
    for (int k = 0; k < 32; k++) {
        u64 xk = pack2(xn[k]);
        #pragma unroll
        for (int m = 0; m < 4; m++) {
            ulonglong2 w = gw2[k * 4 + m];
            fma2(accg[2 * m],     w.x, xk, accg[2 * m]);
            fma2(accg[2 * m + 1], w.y, xk, accg[2 * m + 1]);
        }
    }
    float cm[32];
    #pragma unroll
    for (int jp = 0; jp < 8; jp++) {
        float a0 = lo2(accg[jp]), a1 = hi2(accg[jp]);
        mish_pair(a0, cm[2 * jp],     cm[2 * jp + 16]);
        mish_pair(a1, cm[2 * jp + 1], cm[2 * jp + 17]);
    }
    u64 accr[16];
    #pragma unroll
    for (int cp = 0; cp < 16; cp++) accr[cp] = *(const u64*)&s_rb[2 * cp];
    const ulonglong2* rw2 = (const ulonglong2*)s_rw;
    #pragma unroll
    for (int k = 0; k < 32; k++) {
        u64 ck = pack2(cm[k]);
        #pragma unroll
        for (int m = 0; m < 8; m++) {
            ulonglong2 w = rw2[k * 8 + m];
            fma2(accr[2 * m],     w.x, ck, accr[2 * m]);
            fma2(accr[2 * m + 1], w.y, ck, accr[2 * m + 1]);
        }
    }
    #pragma unroll
    for (int cp = 0; cp < 16; cp++) {
        rn[2 * cp]     = lo2(accr[cp]);
        rn[2 * cp + 1] = hi2(accr[cp]);
    }
}

__global__ void k_prep() {
    int idx = blockIdx.x * 512 + threadIdx.x;
    float* st = &g_statp[0][0][0][0];
    if (idx < NPART * 42 * 2 * 128) st[idx] = 0.f;
}

// start conv (32x256) + layer-0 gate/res + stats[0]
__global__ __launch_bounds__(256, 2) void k_start(
    const float* __restrict__ xin,
    const float* __restrict__ start_w, const float* __restrict__ start_b,
    const float* __restrict__ gate_w, const float* __restrict__ gate_b,
    const float* __restrict__ res_w, const float* __restrict__ res_b)
{
    __shared__ __align__(16) float s_red[256 * 34];   // swT alias / reduction
    __shared__ float s_p1[256], s_p2[256];
    __shared__ __align__(16) float s_gw[512];
    __shared__ __align__(16) float s_rw[1024];
    __shared__ __align__(8) float s_gb[16];
    __shared__ __align__(8) float s_rb[32];
    __shared__ __align__(8) float s_sb[32];

    int tid = threadIdx.x;
    int p = blockIdx.x * 256 + tid;
    int prt = blockIdx.x & (NPART - 1);

    for (int idx = tid; idx < 8192; idx += 256) {
        int k = idx >> 5, c = idx & 31;
        s_red[k * 32 + c] = start_w[c * 256 + k];
    }
    for (int i = tid; i < 512; i += 256)  { int j = i & 15, k = i >> 4; s_gw[i] = gate_w[j * 32 + k]; }
    for (int i = tid; i < 1024; i += 256) { int c = i & 31, k = i >> 5; s_rw[i] = res_w[c * 32 + k]; }
    if (tid < 16) s_gb[tid] = gate_b[tid];
    if (tid >= 32 && tid < 64) s_rb[tid - 32] = res_b[tid - 32];
    if (tid >= 64 && tid < 96) s_sb[tid - 64] = start_b[tid - 64];
    __syncthreads();

    u64 acc[16];
    #pragma unroll
    for (int cp = 0; cp < 16; cp++) acc[cp] = *(const u64*)&s_sb[2 * cp];
    const float* xp = xin + (size_t)(p & 7) * (256 * 8192) + (p >> 3);
    const ulonglong2* swT2 = (const ulonglong2*)s_red;
    #pragma unroll 4
    for (int k = 0; k < 256; k++) {
        u64 xk = pack2(xp[k * 8192]);
        #pragma unroll
        for (int m = 0; m < 8; m++) {
            ulonglong2 w = swT2[k * 8 + m];
            fma2(acc[2 * m],     w.x, xk, acc[2 * m]);
            fma2(acc[2 * m + 1], w.y, xk, acc[2 * m + 1]);
        }
    }
    float xn[32];
    #pragma unroll
    for (int cp = 0; cp < 16; cp++) {
        xn[2 * cp] = lo2(acc[cp]);
        xn[2 * cp + 1] = hi2(acc[cp]);
    }
    float rn[32];
    gate_res_p(xn, rn, s_gw, s_gb, s_rw, s_rb);
    #pragma unroll
    for (int cp = 0; cp < 16; cp++)
        g_xr[cp * NPOS + p] = make_float4(xn[2 * cp], xn[2 * cp + 1],
                                          rn[2 * cp], rn[2 * cp + 1]);

    reduce_stats<256>(s_red, s_p1, s_p2, rn, tid, prt, 0, 0);
}

// ================= layer kernel: BN+res, gate, mish, res, stats =================
__global__ __launch_bounds__(64, 7) void k_layer(
    const float* __restrict__ gate_w, const float* __restrict__ gate_b,
    const float* __restrict__ res_w, const float* __restrict__ res_b,
    const float* __restrict__ bn_g, const float* __restrict__ bn_b,
    int layer)
{
    __shared__ __align__(16) float s_gw[512];    // [k][16] j contiguous
    __shared__ __align__(16) float s_rw[1024];   // [k][32] c contiguous
    __shared__ __align__(16) float4 s_red4[8 * 65];
    __shared__ __align__(16) float4 s_ps[64], s_pq[64];
    __shared__ float s_gb[16], s_rb[32];
    __shared__ float s_scale[32], s_shift[32];

    int tid = threadIdx.x;
    int p = blockIdx.x * 64 + tid;
    int prt = blockIdx.x & (NPART - 1);

    for (int i = tid; i < 512; i += 64)  { int j = i & 15, k = i >> 4; s_gw[i] = gate_w[layer * 512 + j * 32 + k]; }
    for (int i = tid; i < 1024; i += 64) { int c = i & 31, k = i >> 5; s_rw[i] = res_w[layer * 1024 + c * 32 + k]; }
    if (tid < 16) s_gb[tid] = gate_b[layer * 16 + tid];
    if (tid >= 32) s_rb[tid - 32] = res_b[layer * 32 + tid - 32];
    bn_combine32(bn_g + (layer - 1) * 32, bn_b + (layer - 1) * 32, layer - 1,
                 s_scale, s_shift, tid);
    __syncthreads();

    // BN + residual; store x' immediately (frees x before res GEMM)
    float x[32];
    #pragma unroll
    for (int cp = 0; cp < 16; cp++) {
        float4 v = g_xr[cp * NPOS + p];
        float v0 = fmaf(s_scale[2 * cp],     v.z, v.x + s_shift[2 * cp]);
        float v1 = fmaf(s_scale[2 * cp + 1], v.w, v.y + s_shift[2 * cp + 1]);
        x[2 * cp] = v0; x[2 * cp + 1] = v1;
        ((float2*)(g_xr + cp * NPOS + p))[0] = make_float2(v0, v1);
    }

    // gate GEMM 16x32 with full-row prefetch
    u64 accg[8];
    #pragma unroll
    for (int m = 0; m < 8; m++) accg[m] = *(const u64*)&s_gb[2 * m];
    {
        const ulonglong2* gw2 = (const ulonglong2*)s_gw;
        ulonglong2 wc[4];
        #pragma unroll
        for (int m = 0; m < 4; m++) wc[m] = gw2[m];
        #pragma unroll
        for (int k = 0; k < 31; k++) {
            u64 xk = pack2(x[k]);
            ulonglong2 wn[4];
            #pragma unroll
            for (int m = 0; m < 4; m++) wn[m] = gw2[(k + 1) * 4 + m];
            #pragma unroll
            for (int m = 0; m < 4; m++) {
                fma2(accg[2 * m],     wc[m].x, xk, accg[2 * m]);
                fma2(accg[2 * m + 1], wc[m].y, xk, accg[2 * m + 1]);
            }
            #pragma unroll
            for (int m = 0; m < 4; m++) wc[m] = wn[m];
        }
        u64 xk = pack2(x[31]);
        #pragma unroll
        for (int m = 0; m < 4; m++) {
            fma2(accg[2 * m],     wc[m].x, xk, accg[2 * m]);
            fma2(accg[2 * m + 1], wc[m].y, xk, accg[2 * m + 1]);
        }
    }

    float cm[32];
    #pragma unroll
    for (int jp = 0; jp < 8; jp++) {
        float a0 = lo2(accg[jp]), a1 = hi2(accg[jp]);
        mish_pair(a0, cm[2 * jp],     cm[2 * jp + 16]);
        mish_pair(a1, cm[2 * jp + 1], cm[2 * jp + 17]);
    }

    // res GEMM 32x32 with half-row double-buffer prefetch
    u64 accr[16];
    #pragma unroll
    for (int m = 0; m < 16; m++) accr[m] = *(const u64*)&s_rb[2 * m];
    {
        const ulonglong2* rw2 = (const ulonglong2*)s_rw;
        ulonglong2 h[4];
        #pragma unroll
        for (int m = 0; m < 4; m++) h[m] = rw2[m];
        #pragma unroll
        for (int k = 0; k < 32; k++) {
            u64 ck = pack2(cm[k]);
            ulonglong2 g[4];
            #pragma unroll
            for (int m = 0; m < 4; m++) g[m] = rw2[k * 8 + 4 + m];
            #pragma unroll
            for (int m = 0; m < 4; m++) {
                fma2(accr[2 * m],     h[m].x, ck, accr[2 * m]);
                fma2(accr[2 * m + 1], h[m].y, ck, accr[2 * m + 1]);
            }
            if (k < 31) {
                #pragma unroll
                for (int m = 0; m < 4; m++) h[m] = rw2[(k + 1) * 8 + m];
            }
            #pragma unroll
            for (int m = 0; m < 4; m++) {
                fma2(accr[8 + 2 * m], g[m].x, ck, accr[8 + 2 * m]);
                fma2(accr[9 + 2 * m], g[m].y, ck, accr[9 + 2 * m]);
            }
        }
    }

    float rn[32];
    #pragma unroll
    for (int m = 0; m < 16; m++) {
        rn[2 * m]     = lo2(accr[m]);
        rn[2 * m + 1] = hi2(accr[m]);
        ((float2*)(g_xr + m * NPOS + p))[1] = make_float2(rn[2 * m], rn[2 * m + 1]);
    }

    reduce64(s_red4, s_ps, s_pq, rn, tid, prt, layer);
}

// apply BN(39) + residual -> final x into g_xf; stats[40]
__global__ __launch_bounds__(64, 7) void k_endA(
    const float* __restrict__ bn_g, const float* __restrict__ bn_b)
{
    __shared__ __align__(16) float4 s_red4[8 * 65];
    __shared__ __align__(16) float4 s_ps[64], s_pq[64];
    __shared__ float s_scale[32], s_shift[32];
    int tid = threadIdx.x;
    int p = blockIdx.x * 64 + tid;
    int prt = blockIdx.x & (NPART - 1);
    bn_combine32(bn_g + 39 * 32, bn_b + 39 * 32, 39, s_scale, s_shift, tid);
    __syncthreads();
    float xn[32];
    #pragma unroll
    for (int cp = 0; cp < 16; cp++) {
        float4 v = g_xr[cp * NPOS + p];
        xn[2 * cp]     = fmaf(s_scale[2 * cp],     v.z, v.x + s_shift[2 * cp]);
        xn[2 * cp + 1] = fmaf(s_scale[2 * cp + 1], v.w, v.y + s_shift[2 * cp + 1]);
    }
    #pragma unroll
    for (int cq = 0; cq < 8; cq++)
        g_xf[cq * NPOS + p] = make_float4(xn[4 * cq], xn[4 * cq + 1],
                                          xn[4 * cq + 2], xn[4 * cq + 3]);
    reduce64(s_red4, s_ps, s_pq, xn, tid, prt, 40);
}

// tiled end_conv1: z[128] = W1 @ concat_mish(bn1(x)); stats[41]
__global__ __launch_bounds__(256, 3) void k_endB(
    const float* __restrict__ bn1_g, const float* __restrict__ bn1_b,
    const float* __restrict__ w1, const float* __restrict__ b1)
{
    __shared__ __align__(16) float s_w[128 * 68];   // [o][k] pad 68
    __shared__ __align__(16) float s_y[64 * 68];    // [k][pos] pad 68
    __shared__ float s_ps[128 * 17], s_pq[128 * 17];
    __shared__ float s_scale[32], s_shift[32];

    int tid = threadIdx.x;
    int p0 = blockIdx.x * 64;
    int prt = blockIdx.x & (NPART - 1);

    bn_combine32(bn1_g, bn1_b, 40, s_scale, s_shift, tid);

    // stage W (8192 floats)
    #pragma unroll
    for (int i = tid * 4; i < 8192; i += 1024) {
        float4 v = *(const float4*)(w1 + i);
        int o = i >> 6, k = i & 63;
        *(float4*)&s_w[o * 68 + k] = v;
    }
    __syncthreads();   // s_scale ready

    // stage y = concat_mish(bn1(x)) : [64 k][64 pos]
    #pragma unroll
    for (int it = 0; it < 2; it++) {
        int cq = (tid >> 6) + it * 4;   // 0..7
        int pos = tid & 63;
        float4 xq = g_xf[cq * NPOS + p0 + pos];
        float xv[4] = {xq.x, xq.y, xq.z, xq.w};
        #pragma unroll
        for (int u = 0; u < 4; u++) {
            int c = cq * 4 + u;
            float t = fmaf(s_scale[c], xv[u], s_shift[c]);
            float yp, yn;
            mish_pair(t, yp, yn);
            s_y[c * 68 + pos]        = yp;
            s_y[(c + 32) * 68 + pos] = yn;
        }
    }
    __syncthreads();

    int ty = tid >> 4;      // 0..15 -> out base ty*8
    int tx = tid & 15;      // 0..15 -> pos base tx*4
    int o0 = ty * 8;
    u64 acc[8][2];
    #pragma unroll
    for (int i = 0; i < 8; i++) {
        u64 b = pack2(__ldg(b1 + o0 + i));
        acc[i][0] = b; acc[i][1] = b;
    }
    #pragma unroll 8
    for (int k = 0; k < 64; k++) {
        ulonglong2 yv = *(const ulonglong2*)&s_y[k * 68 + tx * 4];
        #pragma unroll
        for (int i = 0; i < 8; i++) {
            u64 w = pack2(s_w[(o0 + i) * 68 + k]);
            fma2(acc[i][0], w, yv.x, acc[i][0]);
            fma2(acc[i][1], w, yv.y, acc[i][1]);
        }
    }
    #pragma unroll
    for (int i = 0; i < 8; i++) {
        float a0 = lo2(acc[i][0]), a1 = hi2(acc[i][0]);
        float a2 = lo2(acc[i][1]), a3 = hi2(acc[i][1]);
        *(float4*)&g_z[(size_t)(o0 + i) * NPOS + p0 + tx * 4] =
            make_float4(a0, a1, a2, a3);
        s_ps[(o0 + i) * 17 + tx] = a0 + a1 + a2 + a3;
        s_pq[(o0 + i) * 17 + tx] =
            fmaf(a0, a0, fmaf(a1, a1, fmaf(a2, a2, a3 * a3)));
    }
    __syncthreads();
    {
        int o = tid & 127, kind = tid >> 7;
        const float* src = kind ? s_pq : s_ps;
        float t = 0.f;
        #pragma unroll
        for (int j = 0; j < 16; j++) t += src[o * 17 + j];
        atomicAdd(stat_ptr(prt, 41, kind) + o, t);
    }
}

// out = end_conv2 (256x256) @ concat_mish(bn2(z)); f32x2 packed FMA.
__global__ __launch_bounds__(256) void k_endC(
    const float* __restrict__ bn2_g, const float* __restrict__ bn2_b,
    const float* __restrict__ w2, const float* __restrict__ b2,
    float* __restrict__ out)
{
    __shared__ __align__(16) float sBuf[256 * 33 + 32 * 64];
    __shared__ float sSc[128], sSh[128], sB2[256];
    float* sW = sBuf;
    float* sV = sBuf + 256 * 33;

    int tid = threadIdx.x;
    int ty = tid >> 3;
    int tx = tid & 7;
    int p0 = blockIdx.x * 64;
    int l0 = p0 >> 3;

    if (tid < 128) {
        float s = 0.f, q = 0.f;
        #pragma unroll
        for (int pp = 0; pp < NPART; pp++) {
            s += g_statp[pp][41][0][tid];
            q += g_statp[pp][41][1][tid];
        }
        float m = s * (1.0f / NPOSf);
        float var = q * (1.0f / NPOSf) - m * m;
        float inv = rsqrtf(var + 1e-5f);
        float sc = bn2_g[tid] * inv;
        sSc[tid] = sc;
        sSh[tid] = bn2_b[tid] - m * sc;
    }
    sB2[tid] = b2[tid];

    u64 acc[8][4];
    #pragma unroll
    for (int i = 0; i < 8; i++)
        #pragma unroll
        for (int jp = 0; jp < 4; jp++) acc[i][jp] = 0ULL;

    for (int kc = 0; kc < 8; kc++) {
        __syncthreads();
        for (int idx = tid; idx < 8192; idx += 256) {
            int o = idx >> 5, k = idx & 31;
            sW[o * 33 + k] = w2[o * 256 + kc * 32 + k];
        }
        for (int idx = tid; idx < 2048; idx += 256) {
            int kk = idx >> 6, qq = idx & 63;
            int c = kc * 32 + kk;
            int zc = (c < 128) ? c : c - 128;
            float t = fmaf(sSc[zc], g_z[zc * NPOS + p0 + qq], sSh[zc]);
            sV[kk * 64 + qq] = mishf((c < 128) ? t : -t);
        }
        __syncthreads();
        int woff = ty * 8 * 33;
        int voff = tx * 8;
        #pragma unroll
        for (int k = 0; k < 32; k++) {
            u64 vv[4];
            #pragma unroll
            for (int jp = 0; jp < 4; jp++)
                vv[jp] = *(const u64*)&sV[k * 64 + voff + jp * 2];
            #pragma unroll
            for (int i = 0; i < 8; i++) {
                u64 wd = pack2(sW[woff + i * 33 + k]);
                #pragma unroll
                for (int jp = 0; jp < 4; jp++)
                    fma2(acc[i][jp], wd, vv[jp], acc[i][jp]);
            }
        }
    }

    for (int oh = 0; oh < 2; oh++) {
        __syncthreads();
        if ((ty >> 4) == oh) {
            int orow = (ty & 15) * 8;
            #pragma unroll
            for (int i = 0; i < 8; i++) {
                float bias = sB2[oh * 128 + orow + i];
                #pragma unroll
                for (int j = 0; j < 8; j++) {
                    int jp = j >> 1;
                    float f = (j & 1) ? hi2(acc[i][jp]) : lo2(acc[i][jp]);
                    sBuf[(orow + i) * 64 + j * 8 + tx] = f + bias;
                }
            }
        }
        __syncthreads();
        for (int idx = tid; idx < 2048; idx += 256) {
            int oloc = idx >> 4;
            int b = (idx >> 1) & 7;
            int hh = idx & 1;
            float4 v = *(float4*)&sBuf[oloc * 64 + b * 8 + hh * 4];
            *(float4*)&out[(size_t)b * 2097152 + (size_t)(oh * 128 + oloc) * 8192
                           + l0 + hh * 4] = v;
        }
    }
}

extern "C" void kernel_launch(void* const* d_in, const int* in_sizes, int n_in,
                              void* d_out, int out_size) {
    const float* x           = (const float*)d_in[0];
    const float* start_w     = (const float*)d_in[1];
    const float* start_b     = (const float*)d_in[2];
    const float* gate_w      = (const float*)d_in[3];
    const float* gate_b      = (const float*)d_in[4];
    const float* res_w       = (const float*)d_in[5];
    const float* res_b       = (const float*)d_in[6];
    const float* bn_g        = (const float*)d_in[7];
    const float* bn_b        = (const float*)d_in[8];
    const float* end_bn1_g   = (const float*)d_in[9];
    const float* end_bn1_b   = (const float*)d_in[10];
    const float* end_conv1_w = (const float*)d_in[11];
    const float* end_conv1_b = (const float*)d_in[12];
    const float* end_bn2_g   = (const float*)d_in[13];
    const float* end_bn2_b   = (const float*)d_in[14];
    const float* end_conv2_w = (const float*)d_in[15];
    const float* end_conv2_b = (const float*)d_in[16];
    float* out = (float*)d_out;

    k_prep<<<336, 512>>>();
    k_start<<<256, 256>>>(x, start_w, start_b, gate_w, gate_b, res_w, res_b);
    for (int i = 1; i < 40; i++)
        k_layer<<<1024, 64>>>(gate_w, gate_b, res_w, res_b, bn_g, bn_b, i);
    k_endA<<<1024, 64>>>(bn_g, bn_b);
    k_endB<<<1024, 256>>>(end_bn1_g, end_bn1_b, end_conv1_w, end_conv1_b);
    k_endC<<<1024, 256>>>(end_bn2_g, end_bn2_b, end_conv2_w, end_conv2_b, out);
}